// round 11
// baseline (speedup 1.0000x reference)
#include <cuda_runtime.h>

// Fixed shapes: B=8,H=8,L=1024,DK=1024,DV=64; L==DK.
#define NROWS  65536         // B*H*L rows of Q/K, 1024 floats = 256 float4 each
#define NTILES 2048          // 32-row tiles per tensor
#define NF4    1048576       // output float4 count (NROWS * 16)
#define GRID   296           // 148 SMs * 2 CTAs, guaranteed co-resident

// __device__ globals: zeroed at module load; g_kcs restored to zero by the
// finalize phase after each consume. Barrier state is generation-based and
// monotonic, so graph replays are deterministic.
__device__ float g_qrs[NROWS];
__device__ float g_krs[NROWS];
__device__ float g_kcs[NROWS];           // colsum, layout [bh][k]
__device__ unsigned g_count;             // barrier arrivals (monotonic)
__device__ volatile unsigned g_release;  // barrier release generation

// elu(x)+1 without predicates: max(x,0) + exp(min(x,0))
__device__ __forceinline__ float elu1(float x) {
    return fmaxf(x, 0.0f) + exp2f(fminf(x, 0.0f) * 1.4426950408889634f);
}

// One tile = 32 rows. 8 warps; warp w owns rows 4w..4w+3; lane ln reads f4
// positions {ln+32j} (8 independent coalesced LDG.128). Rowsum: one 5-shuffle
// chain per row. Colsum (K): 32 reg accumulators/lane, smem combine, 4
// spread atomicAdds/thread.  (Default cache policy: .cs hints measured -6.5us
// regression in R9.)
template <bool DO_COL>
__device__ __forceinline__ void reduce_tile(const float4* __restrict__ X,
                                            int bt, float* __restrict__ rs_out,
                                            float4* __restrict__ scol) {
    const int t  = threadIdx.x;
    const int w  = t >> 5;
    const int ln = t & 31;
    const float4* p = X + (size_t)bt * 8192;     // 32 rows * 256 f4

    float cacc[32];
    if (DO_COL) {
#pragma unroll
        for (int i = 0; i < 32; i++) cacc[i] = 0.0f;
    }

#pragma unroll
    for (int rr = 0; rr < 4; rr++) {
        const int row = w * 4 + rr;
        float4 v[8];
#pragma unroll
        for (int j = 0; j < 8; j++) v[j] = p[row * 256 + ln + 32 * j];

        float s = 0.0f;
#pragma unroll
        for (int j = 0; j < 8; j++) {
            float e0 = elu1(v[j].x), e1 = elu1(v[j].y);
            float e2 = elu1(v[j].z), e3 = elu1(v[j].w);
            if (DO_COL) {
                cacc[4 * j + 0] += e0; cacc[4 * j + 1] += e1;
                cacc[4 * j + 2] += e2; cacc[4 * j + 3] += e3;
            }
            s += (e0 + e1) + (e2 + e3);
        }
        s += __shfl_xor_sync(0xffffffffu, s, 16);
        s += __shfl_xor_sync(0xffffffffu, s, 8);
        s += __shfl_xor_sync(0xffffffffu, s, 4);
        s += __shfl_xor_sync(0xffffffffu, s, 2);
        s += __shfl_xor_sync(0xffffffffu, s, 1);
        if (ln == 0) rs_out[bt * 32 + row] = s;
    }

    if (DO_COL) {
#pragma unroll
        for (int j = 0; j < 8; j++)
            scol[w * 256 + ln + 32 * j] =
                make_float4(cacc[4 * j], cacc[4 * j + 1],
                            cacc[4 * j + 2], cacc[4 * j + 3]);
        __syncthreads();
        float4 a = scol[t];
#pragma unroll
        for (int ww = 1; ww < 8; ww++) {
            float4 b = scol[ww * 256 + t];
            a.x += b.x; a.y += b.y; a.z += b.z; a.w += b.w;
        }
        float* base = g_kcs + (bt >> 5) * 1024 + t * 4;
        atomicAdd(base + 0, a.x);
        atomicAdd(base + 1, a.y);
        atomicAdd(base + 2, a.z);
        atomicAdd(base + 3, a.w);
        __syncthreads();   // scol reused by the next grid-stride tile
    }
}

__global__ __launch_bounds__(256, 2) void fused_kernel(const float4* __restrict__ K,
                                                       const float4* __restrict__ Q,
                                                       const float4* __restrict__ V,
                                                       float4* __restrict__ O) {
    __shared__ float4 scol[8 * 256];   // 32 KB (K phase only)
    const int t = threadIdx.x;

    // Phase 1: K rowsums + colsums
    for (int bt = blockIdx.x; bt < NTILES; bt += GRID)
        reduce_tile<true>(K, bt, g_krs, scol);

    // Phase 2: Q rowsums
    for (int bt = blockIdx.x; bt < NTILES; bt += GRID)
        reduce_tile<false>(Q, bt, g_qrs, scol);

    // Device-wide barrier (generation-based; replay-safe). All 296 CTAs are
    // co-resident by construction (smem 64KB/SM, regs capped by launch_bounds).
    __threadfence();
    __syncthreads();
    if (t == 0) {
        __threadfence();
        unsigned r   = atomicAdd(&g_count, 1);
        unsigned gen = r / GRID;
        if ((r % GRID) == GRID - 1) {
            g_release = gen + 1;
        } else {
            while (g_release < gen + 1) { __nanosleep(64); }
        }
    }
    __syncthreads();

    // Phase 3: out[row,:] = Qrs*Krs / (Qrs*Kcs + eps) * V[row,:]
    // Scalars via __ldcg (produced on other SMs; read coherently from L2).
    // (i&15)==0 lane restores g_kcs to zero for the next replay; the clearing
    // STG is program-order after that thread's own __ldcg of the same word,
    // and each row's 16 readers sit in one half-warp of one block.
    for (int i = blockIdx.x * 256 + t; i < NF4; i += GRID * 256) {
        const int row = i >> 4;
        const float q = __ldcg(g_qrs + row);
        const float k = __ldcg(g_krs + row);
        const float c = __ldcg(g_kcs + row);
        if ((i & 15) == 0) g_kcs[row] = 0.0f;
        const float scale = __fdividef(q * k, fmaf(q, c, 1e-6f));
        float4 v = V[i];
        v.x *= scale; v.y *= scale; v.z *= scale; v.w *= scale;
        O[i] = v;
    }
}

extern "C" void kernel_launch(void* const* d_in, const int* in_sizes, int n_in,
                              void* d_out, int out_size) {
    const float4* Q = (const float4*)d_in[0];
    const float4* K = (const float4*)d_in[1];
    const float4* V = (const float4*)d_in[2];
    float4* O = (float4*)d_out;

    fused_kernel<<<GRID, 256>>>(K, Q, V, O);
}

// round 17
// speedup vs baseline: 1.1228x; 1.1228x over previous
#include <cuda_runtime.h>

// Fixed shapes: B=8,H=8,L=1024,DK=1024,DV=64; L==DK.
#define NROWS  65536         // B*H*L rows of Q/K, 1024 floats = 256 float4 each
#define NTILES 2048          // 32-row tiles per tensor
#define VTILES 4096          // K tiles then Q tiles, one work list
#define NF4    1048576       // output float4 count (NROWS * 16)
#define GRID   740           // 148 SMs * 5 CTAs, exactly co-resident

// __device__ globals: zeroed at module load; g_kcs restored to zero by the
// finalize phase after each consume; barrier is generation-counting ->
// deterministic across graph replays.
__device__ float g_qrs[NROWS];
__device__ float g_krs[NROWS];
__device__ float g_kcs[NROWS];           // colsum, layout [bh][k]
__device__ unsigned g_count;             // barrier arrivals (monotonic)
__device__ volatile unsigned g_release;  // barrier release generation

// elu(x)+1 without predicates: max(x,0) + exp(min(x,0))
__device__ __forceinline__ float elu1(float x) {
    return fmaxf(x, 0.0f) + exp2f(fminf(x, 0.0f) * 1.4426950408889634f);
}

// R1-layout tile (low smem, low regs): 32 rows x 256 f4; thread t owns f4
// column t for every row -> colsum needs only 4 register accumulators and
// 1KB smem for rowsum partials. Loads batched 4 rows deep for MLP while
// keeping regs ~42 (cap 51 at 5 CTA/SM).
template <bool DO_COL>
__device__ __forceinline__ void reduce_tile(const float4* __restrict__ X,
                                            int bt, float* __restrict__ rs_out,
                                            float* __restrict__ sm) {
    const int t  = threadIdx.x;
    const int w  = t >> 5;
    const int ln = t & 31;
    const float4* p = X + (size_t)bt * 8192 + t;   // 32 rows * 256 f4/row

    float c0 = 0.f, c1 = 0.f, c2 = 0.f, c3 = 0.f;

#pragma unroll
    for (int rb = 0; rb < 8; rb++) {
        float4 v0 = p[(rb * 4 + 0) * 256];
        float4 v1 = p[(rb * 4 + 1) * 256];
        float4 v2 = p[(rb * 4 + 2) * 256];
        float4 v3 = p[(rb * 4 + 3) * 256];
#pragma unroll
        for (int j = 0; j < 4; j++) {
            float4 v = (j == 0) ? v0 : (j == 1) ? v1 : (j == 2) ? v2 : v3;
            float e0 = elu1(v.x), e1 = elu1(v.y), e2 = elu1(v.z), e3 = elu1(v.w);
            if (DO_COL) { c0 += e0; c1 += e1; c2 += e2; c3 += e3; }
            float s = (e0 + e1) + (e2 + e3);
            s += __shfl_xor_sync(0xffffffffu, s, 16);
            s += __shfl_xor_sync(0xffffffffu, s, 8);
            s += __shfl_xor_sync(0xffffffffu, s, 4);
            s += __shfl_xor_sync(0xffffffffu, s, 2);
            s += __shfl_xor_sync(0xffffffffu, s, 1);
            if (ln == 0) sm[(rb * 4 + j) * 8 + w] = s;
        }
    }
    __syncthreads();

    if (t < 32) {
        float s = 0.f;
#pragma unroll
        for (int i = 0; i < 8; i++) s += sm[t * 8 + i];
        rs_out[bt * 32 + t] = s;
    }

    if (DO_COL) {
        float* base = g_kcs + (bt >> 5) * 1024 + t * 4;
        atomicAdd(base + 0, c0);
        atomicAdd(base + 1, c1);
        atomicAdd(base + 2, c2);
        atomicAdd(base + 3, c3);
    }
    __syncthreads();   // sm reused by the next grid-stride tile
}

__global__ __launch_bounds__(256, 5) void fused_kernel(const float4* __restrict__ K,
                                                       const float4* __restrict__ Q,
                                                       const float4* __restrict__ V,
                                                       float4* __restrict__ O) {
    __shared__ float sm[32 * 8];   // 1KB
    const int t = threadIdx.x;

    // One interleaved work list: tiles 0..2047 = K (rowsum+colsum),
    // 2048..4095 = Q (rowsum). No barrier needed between them.
    for (int vt = blockIdx.x; vt < VTILES; vt += GRID) {
        if (vt < NTILES) reduce_tile<true >(K, vt,          g_krs, sm);
        else             reduce_tile<false>(Q, vt - NTILES, g_qrs, sm);
    }

    // Device-wide barrier (generation-based; all 740 CTAs co-resident:
    // 5 CTA/SM via launch_bounds reg cap 51, smem 5KB/SM).
    __threadfence();
    __syncthreads();
    if (t == 0) {
        __threadfence();
        unsigned r   = atomicAdd(&g_count, 1);
        unsigned gen = r / GRID;
        if ((r % GRID) == GRID - 1) {
            g_release = gen + 1;
        } else {
            while (g_release < gen + 1) { __nanosleep(64); }
        }
    }
    __syncthreads();

    // Finalize: out[row,:] = Qrs*Krs / (Qrs*Kcs + eps) * V[row,:]
    // Scalars via __ldcg (produced on other SMs, post-fence). (i&15)==0 lane
    // restores g_kcs for the next replay; its clearing STG is program-order
    // after its own __ldcg of the same word.
    for (int i = blockIdx.x * 256 + t; i < NF4; i += GRID * 256) {
        const int row = i >> 4;
        const float q = __ldcg(g_qrs + row);
        const float k = __ldcg(g_krs + row);
        const float c = __ldcg(g_kcs + row);
        if ((i & 15) == 0) g_kcs[row] = 0.0f;
        const float scale = __fdividef(q * k, fmaf(q, c, 1e-6f));
        float4 v = V[i];
        v.x *= scale; v.y *= scale; v.z *= scale; v.w *= scale;
        O[i] = v;
    }
}

extern "C" void kernel_launch(void* const* d_in, const int* in_sizes, int n_in,
                              void* d_out, int out_size) {
    const float4* Q = (const float4*)d_in[0];
    const float4* K = (const float4*)d_in[1];
    const float4* V = (const float4*)d_in[2];
    float4* O = (float4*)d_out;

    fused_kernel<<<GRID, 256>>>(K, Q, V, O);
}